// round 4
// baseline (speedup 1.0000x reference)
#include <cuda_runtime.h>

// Bilateral filter 9x9, sigma_s=3, sigma_r=0.1, reflect padding, 4096x4096 fp32.
//
// w = exp2( Ls(dx,dy) - K2*(win-c)^2 ),  K2 = 50*log2(e)
// expanded: arg = (-K2*win + a)*win + b,  a = 2*K2*c, b = -K2*c^2
//
// Round-4: 2 pixels/thread; tap k of px0 pairs with tap k of px1 -> adjacent
// floats (f[k], f[k+1]). A second SMEM tile shifted by one float makes EVERY
// pair an aligned LDS.64 (even k from tA, odd k from tB) -> zero pair-
// marshalling MOVs. Packed f32x2 FFMA for polynomial + accumulators; scalar
// FADD-imm (in place on pair halves) for the spatial term; scalar MUFU EX2.

#define IMG_H 4096
#define IMG_W 4096
#define RAD 4
#define BX 32
#define BY 8
#define PXW 2
#define TILE_PW (BX * PXW)        // 64
#define TW (TILE_PW + 2*RAD)      // 72 floats (288B row stride, 8B-aligned)
#define TH (BY + 2*RAD)           // 16

__device__ __forceinline__ float ex2f(float x) {
    float y;
    asm("ex2.approx.f32 %0, %1;" : "=f"(y) : "f"(x));
    return y;
}

__device__ __forceinline__ float2 fma2(float2 a, float2 b, float2 c) {
    float2 d;
    asm("fma.rn.f32x2 %0, %1, %2, %3;"
        : "=l"(reinterpret_cast<unsigned long long&>(d))
        : "l"(reinterpret_cast<unsigned long long&>(a)),
          "l"(reinterpret_cast<unsigned long long&>(b)),
          "l"(reinterpret_cast<unsigned long long&>(c)));
    return d;
}

__device__ __forceinline__ float2 add2(float2 a, float2 b) {
    float2 d;
    asm("add.rn.f32x2 %0, %1, %2;"
        : "=l"(reinterpret_cast<unsigned long long&>(d))
        : "l"(reinterpret_cast<unsigned long long&>(a)),
          "l"(reinterpret_cast<unsigned long long&>(b)));
    return d;
}

__global__ __launch_bounds__(BX * BY, 6)
void bilateral_kernel(const float* __restrict__ img, float* __restrict__ out) {
    __shared__ __align__(16) float tA[TH][TW];
    __shared__ __align__(16) float tB[TH][TW];   // tB[r][c] = tA[r][c+1]

    const int tx = threadIdx.x;
    const int ty = threadIdx.y;
    const int bx0 = blockIdx.x * TILE_PW;
    const int by0 = blockIdx.y * BY;

    // ---- tile fill (reflect), also writes the one-float-shifted copy ----
    #pragma unroll
    for (int r = ty; r < TH; r += BY) {
        int gy = by0 + r - RAD;
        gy = (gy < 0) ? -gy : ((gy >= IMG_H) ? (2 * IMG_H - 2 - gy) : gy);
        const float* __restrict__ src = img + (size_t)gy * IMG_W;
        #pragma unroll
        for (int c = tx; c < TW; c += BX) {
            int gx = bx0 + c - RAD;
            gx = (gx < 0) ? -gx : ((gx >= IMG_W) ? (2 * IMG_W - 2 - gx) : gx);
            float v = src[gx];
            tA[r][c] = v;
            if (c >= 1) tB[r][c - 1] = v;
        }
    }
    __syncthreads();

    const float K2 = 72.13475204444817f;                  // 50 * log2(e)
    const float LOG2E_OVER_S = 1.4426950408889634f / 18.0f;

    const int cb = tx * PXW;   // even -> all pair loads 8B-aligned

    // centers: tA[ty+4][cb+4], [cb+5]
    const float c0 = tA[ty + RAD][cb + 4];
    const float c1 = tA[ty + RAD][cb + 5];

    const float2 nK2_2 = make_float2(-K2, -K2);
    const float2 a2    = make_float2(2.0f * K2 * c0, 2.0f * K2 * c1);
    const float2 b2    = make_float2(-K2 * c0 * c0, -K2 * c1 * c1);

    float2 num2 = make_float2(0.f, 0.f);
    float2 den2 = make_float2(0.f, 0.f);

    #pragma unroll
    for (int dy = 0; dy < 9; dy++) {
        const float2* __restrict__ rA =
            reinterpret_cast<const float2*>(&tA[ty + dy][cb]);
        const float2* __restrict__ rB =
            reinterpret_cast<const float2*>(&tB[ty + dy][cb]);

        #pragma unroll
        for (int k = 0; k < 9; k++) {
            // (f[k], f[k+1]) as one aligned LDS.64 — no marshalling
            const float2 win2 = (k & 1) ? rB[(k - 1) >> 1] : rA[k >> 1];

            float2 t2 = fma2(nK2_2, win2, a2);    // packed FFMA
            float2 g2 = fma2(win2, t2, b2);       // packed FFMA

            const float Ls = -(float)((k - 4) * (k - 4) + (dy - 4) * (dy - 4))
                             * LOG2E_OVER_S;
            // scalar FADD-imm in place on pair halves, then scalar MUFU
            float w0 = ex2f(g2.x + Ls);
            float w1 = ex2f(g2.y + Ls);
            float2 w2 = make_float2(w0, w1);

            num2 = fma2(w2, win2, num2);
            den2 = add2(den2, w2);
        }
    }

    float2 o;
    o.x = __fdividef(num2.x, den2.x);
    o.y = __fdividef(num2.y, den2.y);
    *reinterpret_cast<float2*>(&out[(size_t)(by0 + ty) * IMG_W + bx0 + cb]) = o;
}

extern "C" void kernel_launch(void* const* d_in, const int* in_sizes, int n_in,
                              void* d_out, int out_size) {
    const float* img = (const float*)d_in[0];
    float* out = (float*)d_out;
    dim3 block(BX, BY);
    dim3 grid(IMG_W / TILE_PW, IMG_H / BY);
    bilateral_kernel<<<grid, block>>>(img, out);
}

// round 5
// speedup vs baseline: 1.6925x; 1.6925x over previous
#include <cuda_runtime.h>

// Bilateral filter 9x9, sigma_s=3, sigma_r=0.1, reflect padding, 4096x4096 fp32.
//
// w = exp2( Ls(dx,dy) - K2*(win-c)^2 ),  K2 = 50*log2(e)
// expanded: arg = (-K2*win + a)*win + (b + Ls),  a = 2*K2*c, b = -K2*c^2
//
// Round-5: back to R1's all-scalar structure (best: 392us, issue-bound at
// 90.4%), adding vertical register reuse: 2 pixels/thread stacked in y.
// Each window row's 9 floats are loaded into registers ONCE and feed both
// pixels' taps -> LDS/px drops 81 -> 45. No f32x2, no pairing (R3/R4 showed
// ptxas marshalling eats those wins).

#define IMG_H 4096
#define IMG_W 4096
#define RAD 4
#define BX 32
#define BY 8
#define PY 2                       // vertical pixels per thread
#define TILE_PH (BY * PY)          // 16 pixel rows per block
#define TW (BX + 2*RAD)            // 40
#define TH (TILE_PH + 2*RAD)       // 24

__device__ __forceinline__ float ex2f(float x) {
    float y;
    asm("ex2.approx.f32 %0, %1;" : "=f"(y) : "f"(x));
    return y;
}

__global__ __launch_bounds__(BX * BY)
void bilateral_kernel(const float* __restrict__ img, float* __restrict__ out) {
    __shared__ float tile[TH][TW];

    const int tx = threadIdx.x;
    const int ty = threadIdx.y;
    const int bx0 = blockIdx.x * BX;
    const int by0 = blockIdx.y * TILE_PH;

    // ---- tile fill: warp-per-row strided, no division, reflect at edges ----
    #pragma unroll
    for (int r = ty; r < TH; r += BY) {
        int gy = by0 + r - RAD;
        gy = (gy < 0) ? -gy : ((gy >= IMG_H) ? (2 * IMG_H - 2 - gy) : gy);
        const float* __restrict__ src = img + (size_t)gy * IMG_W;
        #pragma unroll
        for (int c = tx; c < TW; c += BX) {
            int gx = bx0 + c - RAD;
            gx = (gx < 0) ? -gx : ((gx >= IMG_W) ? (2 * IMG_W - 2 - gx) : gx);
            tile[r][c] = src[gx];
        }
    }
    __syncthreads();

    const float K2 = 72.13475204444817f;                   // 50 * log2(e)
    const float LOG2E_OVER_S = 1.4426950408889634f / 18.0f;

    // this thread's two pixels: rows py0 = ty*2, py0+1 (within block tile)
    const int py0 = ty * PY;

    // centers: tile[py0+4][tx+4] and tile[py0+5][tx+4]
    const float c0 = tile[py0 + RAD][tx + RAD];
    const float c1 = tile[py0 + RAD + 1][tx + RAD];

    const float a0 = 2.0f * K2 * c0, b0 = -K2 * c0 * c0;
    const float a1 = 2.0f * K2 * c1, b1 = -K2 * c1 * c1;

    float num0 = 0.f, den0 = 0.f;
    float num1 = 0.f, den1 = 0.f;

    // window rows 0..9 relative to py0: row r serves px0 taps (if r<=8,
    // spatial row offset r-4) and px1 taps (if r>=1, spatial offset r-5).
    #pragma unroll
    for (int r = 0; r < 10; r++) {
        // load this window row once into registers (9 scalar LDS)
        float f[9];
        #pragma unroll
        for (int k = 0; k < 9; k++) f[k] = tile[py0 + r][tx + k];

        if (r <= 8) {
            const int dyq0 = (r - 4) * (r - 4);
            #pragma unroll
            for (int k = 0; k < 9; k++) {
                const float win = f[k];
                const float Ls = -(float)((k - 4) * (k - 4) + dyq0) * LOG2E_OVER_S;
                const float btap = b0 + Ls;            // CSE'd: 15 distinct/px
                const float t   = fmaf(-K2, win, a0);  // FFMA-imm (rt=1)
                const float arg = fmaf(win, t, btap);
                const float w   = ex2f(arg);           // MUFU.EX2
                num0 = fmaf(w, win, num0);
                den0 += w;
            }
        }
        if (r >= 1) {
            const int dyq1 = (r - 5) * (r - 5);
            #pragma unroll
            for (int k = 0; k < 9; k++) {
                const float win = f[k];
                const float Ls = -(float)((k - 4) * (k - 4) + dyq1) * LOG2E_OVER_S;
                const float btap = b1 + Ls;
                const float t   = fmaf(-K2, win, a1);
                const float arg = fmaf(win, t, btap);
                const float w   = ex2f(arg);
                num1 = fmaf(w, win, num1);
                den1 += w;
            }
        }
    }

    const size_t o0 = (size_t)(by0 + py0) * IMG_W + bx0 + tx;
    out[o0]         = __fdividef(num0, den0);
    out[o0 + IMG_W] = __fdividef(num1, den1);
}

extern "C" void kernel_launch(void* const* d_in, const int* in_sizes, int n_in,
                              void* d_out, int out_size) {
    const float* img = (const float*)d_in[0];
    float* out = (float*)d_out;
    dim3 block(BX, BY);
    dim3 grid(IMG_W / BX, IMG_H / TILE_PH);
    bilateral_kernel<<<grid, block>>>(img, out);
}